// round 3
// baseline (speedup 1.0000x reference)
#include <cuda_runtime.h>

// PaddingBottleneck: B=32, T=2048, E=1024 fp32.
// out[b,t,0]   = x[b,t,0] * (1 + |padding_amount|)
// out[b,t,1:]  = sigmoid(sum|x[b,t,1:]| - x[b,t,0]) * x[b,t,1:]
//
// One CTA per (b,t) row. 256 threads x float4 = 1024 floats, single pass.
// HBM-bound: 512 MB total traffic -> floor ~75 us at ~7 TB/s achieved.

static constexpr int E = 1024;
static constexpr int THREADS = 256;   // E/4 float4 lanes

__global__ __launch_bounds__(THREADS)
void padding_bottleneck_kernel(const float* __restrict__ x,
                               const float* __restrict__ padding_amount,
                               float* __restrict__ out)
{
    const long long row = blockIdx.x;
    const float4* __restrict__ xin =
        reinterpret_cast<const float4*>(x + row * (long long)E);
    float4* __restrict__ yout =
        reinterpret_cast<float4*>(out + row * (long long)E);

    const int t = threadIdx.x;

    // Issue the scalar load early; it's L2-resident after the first CTA and
    // its latency overlaps the row reduction.
    const float pa_scale = 1.0f + fabsf(__ldg(padding_amount));

    // Single coalesced 128-bit load; whole row stays in registers.
    float4 v = xin[t];

    // Per-thread partial of sum(|x|) over ALL 1024 elements.
    float s = fabsf(v.x) + fabsf(v.y) + fabsf(v.z) + fabsf(v.w);

    // Warp reduction.
    #pragma unroll
    for (int o = 16; o > 0; o >>= 1)
        s += __shfl_xor_sync(0xffffffffu, s, o);

    __shared__ float warp_sums[THREADS / 32];
    __shared__ float s_pad;

    if (t == 0) s_pad = v.x;                 // pad = x[row, 0]
    const int lane = t & 31;
    const int wid  = t >> 5;
    if (lane == 0) warp_sums[wid] = s;
    __syncthreads();

    // Every thread sums the 8 warp partials (broadcast reads, conflict-free).
    float total = 0.0f;
    #pragma unroll
    for (int i = 0; i < THREADS / 32; i++) total += warp_sums[i];

    const float pad = s_pad;
    const float sn  = total - fabsf(pad);    // exclude element 0 from the norm

    // weights = softmax([pad, sn]); one_minus = 1 - weights[0]
    //         = 1 / (1 + exp(pad - sn))   (exact, overflow-safe in fp32)
    const float one_minus = 1.0f / (1.0f + __expf(pad - sn));

    float4 r;
    r.x = v.x * one_minus;
    r.y = v.y * one_minus;
    r.z = v.z * one_minus;
    r.w = v.w * one_minus;

    if (t == 0) {
        // Element 0: pad * (1 + |padding_amount|)
        r.x = pad * pa_scale;
    }

    yout[t] = r;   // single coalesced 128-bit store
}

extern "C" void kernel_launch(void* const* d_in, const int* in_sizes, int n_in,
                              void* d_out, int out_size)
{
    // metadata order is (x, padding_amount); guard against slot swap by
    // selecting on element counts (x is huge, padding_amount is 1 element).
    const float* x  = (const float*)d_in[0];
    const float* pa = (const float*)d_in[1];
    int nx = in_sizes[0];
    if (n_in >= 2 && in_sizes[1] > in_sizes[0]) {
        x  = (const float*)d_in[1];
        pa = (const float*)d_in[0];
        nx = in_sizes[1];
    }
    float* out = (float*)d_out;

    const int rows = nx / E;                          // 65536
    padding_bottleneck_kernel<<<rows, THREADS>>>(x, pa, out);
}

// round 10
// speedup vs baseline: 1.0728x; 1.0728x over previous
#include <cuda_runtime.h>

// PaddingBottleneck: B=32, T=2048, E=1024 fp32.
// out[b,t,0]   = x[b,t,0] * (1 + |padding_amount|)
// out[b,t,1:]  = sigmoid(sum|x[b,t,1:]| - x[b,t,0]) * x[b,t,1:]
//
// Warp-per-row: each warp owns one 1024-float row. Lane l loads float4
// indices {l, l+32, ..., l+224} (8 coalesced LDG.128, all independent ->
// MLP=8). Reduction is warp-shuffle only: no smem, no __syncthreads.
// 8 warps/CTA -> 8192 CTAs.

static constexpr int E          = 1024;
static constexpr int VEC_PER_ROW = E / 4;     // 256 float4
static constexpr int V_PER_LANE  = VEC_PER_ROW / 32;  // 8
static constexpr int WARPS_PER_CTA = 8;
static constexpr int THREADS   = WARPS_PER_CTA * 32;  // 256

__global__ __launch_bounds__(THREADS)
void padding_bottleneck_kernel(const float* __restrict__ x,
                               const float* __restrict__ padding_amount,
                               float* __restrict__ out)
{
    const int lane = threadIdx.x & 31;
    const int warp = threadIdx.x >> 5;
    const long long row = (long long)blockIdx.x * WARPS_PER_CTA + warp;

    const float4* __restrict__ xin =
        reinterpret_cast<const float4*>(x + row * (long long)E);
    float4* __restrict__ yout =
        reinterpret_cast<float4*>(out + row * (long long)E);

    // Scalar: L2-resident after first access; latency overlaps the loads.
    const float pa_scale = 1.0f + fabsf(__ldg(padding_amount));

    // 8 independent 128-bit loads, issued back-to-back (MLP=8).
    float4 v[V_PER_LANE];
    #pragma unroll
    for (int j = 0; j < V_PER_LANE; j++)
        v[j] = xin[lane + 32 * j];

    // Per-lane partial of sum(|x|) over the whole row.
    float s = 0.0f;
    #pragma unroll
    for (int j = 0; j < V_PER_LANE; j++)
        s += fabsf(v[j].x) + fabsf(v[j].y) + fabsf(v[j].z) + fabsf(v[j].w);

    // Warp-shuffle reduction (no smem, no barriers).
    #pragma unroll
    for (int o = 16; o > 0; o >>= 1)
        s += __shfl_xor_sync(0xffffffffu, s, o);

    // pad = x[row, 0] lives in lane 0's v[0].x; broadcast it.
    const float pad = __shfl_sync(0xffffffffu, v[0].x, 0);
    const float sn  = s - fabsf(pad);        // exclude element 0 from the norm

    // softmax([pad, sn]); one_minus = 1 - w0 = 1 / (1 + exp(pad - sn))
    const float one_minus = 1.0f / (1.0f + __expf(pad - sn));

    // Scale and store (8 coalesced STG.128).
    #pragma unroll
    for (int j = 0; j < V_PER_LANE; j++) {
        float4 r;
        r.x = v[j].x * one_minus;
        r.y = v[j].y * one_minus;
        r.z = v[j].z * one_minus;
        r.w = v[j].w * one_minus;
        if (j == 0 && lane == 0)
            r.x = pad * pa_scale;            // element 0 override
        yout[lane + 32 * j] = r;
    }
}

extern "C" void kernel_launch(void* const* d_in, const int* in_sizes, int n_in,
                              void* d_out, int out_size)
{
    // metadata order is (x, padding_amount); guard against slot swap by
    // selecting on element counts (x is huge, padding_amount is 1 element).
    const float* x  = (const float*)d_in[0];
    const float* pa = (const float*)d_in[1];
    int nx = in_sizes[0];
    if (n_in >= 2 && in_sizes[1] > in_sizes[0]) {
        x  = (const float*)d_in[1];
        pa = (const float*)d_in[0];
        nx = in_sizes[1];
    }
    float* out = (float*)d_out;

    const int rows = nx / E;                          // 65536
    padding_bottleneck_kernel<<<rows / WARPS_PER_CTA, THREADS>>>(x, pa, out);
}